// round 6
// baseline (speedup 1.0000x reference)
#include <cuda_runtime.h>
#include <cstdint>
#include <cstddef>

#define NN   100000
#define IND  128
#define HID  64
#define OUTD 128
#define ECAP 1700000

// Scratch (device globals — no allocation allowed)
__device__ __align__(16) float g_y1[(size_t)NN * HID];   // x @ w1_l
__device__ __align__(16) float g_xr[(size_t)NN * HID];   // x @ w1_r
__device__ __align__(16) float g_h [(size_t)NN * HID];   // layer-1 activations
__device__ __align__(16) float g_mh[(size_t)NN * HID];   // mean of h over neighbors
__device__ __align__(16) float g_rinv[NN];               // 1 / max(deg, 1)
__device__ __align__(16) int   g_deg[NN];
__device__ int   g_cur[NN];
__device__ int   g_off[NN + 1];
__device__ int   g_eidx[ECAP];                           // src node per CSR slot

// ---------------------------------------------------------------------------
__global__ void k_init() {
    int i = blockIdx.x * blockDim.x + threadIdx.x;
    if (i < NN) { g_deg[i] = 0; g_cur[i] = 0; }
}

__global__ void k_deg(const int* __restrict__ dst, int E) {
    int e = blockIdx.x * blockDim.x + threadIdx.x;
    if (e < E) {
        int d = dst[e];
        if (d >= 0 && d < NN) atomicAdd(&g_deg[d], 1);
    }
}

// ---------------------------------------------------------------------------
// Single-block exclusive scan over degrees -> g_off; also g_rinv.
// chunk = 100 (multiple of 4) so every thread's int4 loads are 16B-aligned.
// ---------------------------------------------------------------------------
__global__ __launch_bounds__(1024) void k_scan() {
    __shared__ int ssum[1024];
    const int T = 1024;
    const int chunk = 100;                 // 1024*100 >= NN; multiple of 4
    int t = threadIdx.x;
    int beg = t * chunk;
    int end = min(beg + chunk, NN);

    int s = 0;
    if (beg < NN) {
        int i = beg;
        int endv = beg + ((end - beg) & ~3);
        for (; i < endv; i += 4) {
            int4 v = *(const int4*)&g_deg[i];
            s += v.x + v.y + v.z + v.w;
        }
        for (; i < end; i++) s += g_deg[i];
    }
    ssum[t] = s;
    __syncthreads();

    for (int d = 1; d < T; d <<= 1) {
        int v = (t >= d) ? ssum[t - d] : 0;
        __syncthreads();
        ssum[t] += v;
        __syncthreads();
    }
    int run = (t == 0) ? 0 : ssum[t - 1];

    for (int k = beg; k < end; k++) {
        int dgi = g_deg[k];
        g_off[k] = run;
        g_rinv[k] = 1.0f / fmaxf((float)dgi, 1.0f);
        run += dgi;
    }
    if (t == T - 1) g_off[NN] = run;
}

__global__ void k_fill(const int* __restrict__ src,
                       const int* __restrict__ dst, int E) {
    int e = blockIdx.x * blockDim.x + threadIdx.x;
    if (e >= E) return;
    int d = dst[e];
    int s = src[e];
    if (d < 0 || d >= NN || s < 0 || s >= NN) return;
    int pos = g_off[d] + atomicAdd(&g_cur[d], 1);
    if (pos >= 0 && pos < ECAP) g_eidx[pos] = s;
}

// ---------------------------------------------------------------------------
// Layer-1 fused GEMM, 2 rows per iteration:
//   y1 = x @ w1_l, xr = x @ w1_r   (x:[NN,128], w:[128,64])
// j = warp*16 + lane%16 -> output column (j<64: w1_l, else w1_r);
// kh = lane/16 -> K-half, pair-reduced with shfl_xor(16).
// ---------------------------------------------------------------------------
__global__ __launch_bounds__(256) void k_gemm1(
    const float* __restrict__ x,
    const float* __restrict__ w1l,
    const float* __restrict__ w1r,
    int n)
{
    int tid  = threadIdx.x;
    int lane = tid & 31;
    int warp = tid >> 5;
    int j    = warp * 16 + (lane & 15);
    int kh   = lane >> 4;

    const float* w = (j < 64) ? w1l : w1r;
    int col = (j < 64) ? j : (j - 64);

    float wc[64];
#pragma unroll
    for (int k = 0; k < 64; k++)
        wc[k] = __ldg(&w[(size_t)(kh * 64 + k) * 64 + col]);

    for (int i = blockIdx.x * 2; i < n; i += gridDim.x * 2) {
        bool two = (i + 1 < n);
        const float4* xa = (const float4*)(x + (size_t)i * IND + kh * 64);
        const float4* xb = two ? (const float4*)(x + (size_t)(i + 1) * IND + kh * 64) : xa;
        float a0 = 0.f, a1 = 0.f, a2 = 0.f, a3 = 0.f;
        float c0 = 0.f, c1 = 0.f, c2 = 0.f, c3 = 0.f;
#pragma unroll
        for (int k4 = 0; k4 < 16; k4++) {
            float4 va = __ldg(xa + k4);
            float4 vb = __ldg(xb + k4);
            a0 = fmaf(va.x, wc[4 * k4 + 0], a0);
            a1 = fmaf(va.y, wc[4 * k4 + 1], a1);
            a2 = fmaf(va.z, wc[4 * k4 + 2], a2);
            a3 = fmaf(va.w, wc[4 * k4 + 3], a3);
            c0 = fmaf(vb.x, wc[4 * k4 + 0], c0);
            c1 = fmaf(vb.y, wc[4 * k4 + 1], c1);
            c2 = fmaf(vb.z, wc[4 * k4 + 2], c2);
            c3 = fmaf(vb.w, wc[4 * k4 + 3], c3);
        }
        float accA = (a0 + a1) + (a2 + a3);
        float accB = (c0 + c1) + (c2 + c3);
        accA += __shfl_xor_sync(0xffffffffu, accA, 16);
        accB += __shfl_xor_sync(0xffffffffu, accB, 16);
        if (kh == 0) {
            if (j < 64) {
                g_y1[(size_t)i * HID + j] = accA;
                if (two) g_y1[(size_t)(i + 1) * HID + j] = accB;
            } else {
                g_xr[(size_t)i * HID + (j - 64)] = accA;
                if (two) g_xr[(size_t)(i + 1) * HID + (j - 64)] = accB;
            }
        }
    }
}

// ---------------------------------------------------------------------------
// Gather-side aggregation, one warp per node, float4 gathers.
// 16 lanes cover the 64-float row in one LDG.128; half-warps own even/odd
// CSR slots; 2x unroll -> 4 independent 256B loads in flight per warp.
// layer 0: g_h  = relu(mean(g_y1[nbrs]) + b1 + g_xr)
// layer 1: g_mh = mean(g_h[nbrs])
// ---------------------------------------------------------------------------
__global__ __launch_bounds__(256) void k_agg(const float* __restrict__ b1,
                                             int layer)
{
    int node = blockIdx.x * 8 + (threadIdx.x >> 5);
    if (node >= NN) return;
    int lane = threadIdx.x & 31;
    int q    = lane & 15;     // float4 slot within row
    int half = lane >> 4;     // even/odd edge stream

    const float* val = (layer == 0) ? g_y1 : g_h;
    int beg = g_off[node];
    int end = g_off[node + 1];

    float4 A = {0.f, 0.f, 0.f, 0.f};
    float4 B = {0.f, 0.f, 0.f, 0.f};
    int e = beg + half;
    for (; e + 2 < end; e += 4) {
        int s0 = __ldg(&g_eidx[e]);
        int s1 = __ldg(&g_eidx[e + 2]);
        float4 v0 = __ldg((const float4*)(val + (size_t)s0 * HID) + q);
        float4 v1 = __ldg((const float4*)(val + (size_t)s1 * HID) + q);
        A.x += v0.x; A.y += v0.y; A.z += v0.z; A.w += v0.w;
        B.x += v1.x; B.y += v1.y; B.z += v1.z; B.w += v1.w;
    }
    if (e < end) {
        int s = __ldg(&g_eidx[e]);
        float4 v = __ldg((const float4*)(val + (size_t)s * HID) + q);
        A.x += v.x; A.y += v.y; A.z += v.z; A.w += v.w;
    }
    float4 acc;
    acc.x = A.x + B.x; acc.y = A.y + B.y; acc.z = A.z + B.z; acc.w = A.w + B.w;
    acc.x += __shfl_xor_sync(0xffffffffu, acc.x, 16);
    acc.y += __shfl_xor_sync(0xffffffffu, acc.y, 16);
    acc.z += __shfl_xor_sync(0xffffffffu, acc.z, 16);
    acc.w += __shfl_xor_sync(0xffffffffu, acc.w, 16);

    if (half == 0) {
        float r = g_rinv[node];
        if (layer == 0) {
            float4 xv = ((const float4*)(g_xr + (size_t)node * HID))[q];
            float4 bb = __ldg((const float4*)b1 + q);
            float4 h;
            h.x = fmaxf(fmaf(acc.x, r, bb.x + xv.x), 0.f);
            h.y = fmaxf(fmaf(acc.y, r, bb.y + xv.y), 0.f);
            h.z = fmaxf(fmaf(acc.z, r, bb.z + xv.z), 0.f);
            h.w = fmaxf(fmaf(acc.w, r, bb.w + xv.w), 0.f);
            ((float4*)(g_h + (size_t)node * HID))[q] = h;
        } else {
            float4 m;
            m.x = acc.x * r; m.y = acc.y * r; m.z = acc.z * r; m.w = acc.w * r;
            ((float4*)(g_mh + (size_t)node * HID))[q] = m;
        }
    }
}

// ---------------------------------------------------------------------------
// Layer-2 fused output, 2 rows per iteration:
//   out = g_mh @ w2_l + b2 + g_h @ w2_r
// kh=0 -> mh/w2_l branch, kh=1 -> h/w2_r branch; pair-reduced via shfl.
// ---------------------------------------------------------------------------
__global__ __launch_bounds__(256) void k_out(
    const float* __restrict__ w2l,
    const float* __restrict__ w2r,
    const float* __restrict__ b2,
    float* __restrict__ out,
    int n)
{
    int tid  = threadIdx.x;
    int lane = tid & 31;
    int warp = tid >> 5;
    int j    = warp * 16 + (lane & 15);
    int kh   = lane >> 4;

    const float* w = (kh == 0) ? w2l : w2r;   // [64,128]
    float wc[64];
#pragma unroll
    for (int k = 0; k < 64; k++)
        wc[k] = __ldg(&w[(size_t)k * 128 + j]);

    float bj = __ldg(b2 + j);

    const float* base = (kh == 0) ? g_mh : g_h;

    for (int i = blockIdx.x * 2; i < n; i += gridDim.x * 2) {
        bool two = (i + 1 < n);
        const float4* sa = (const float4*)(base + (size_t)i * HID);
        const float4* sb = two ? (const float4*)(base + (size_t)(i + 1) * HID) : sa;
        float a0 = 0.f, a1 = 0.f, a2 = 0.f, a3 = 0.f;
        float c0 = 0.f, c1 = 0.f, c2 = 0.f, c3 = 0.f;
#pragma unroll
        for (int k4 = 0; k4 < 16; k4++) {
            float4 va = __ldg(sa + k4);
            float4 vb = __ldg(sb + k4);
            a0 = fmaf(va.x, wc[4 * k4 + 0], a0);
            a1 = fmaf(va.y, wc[4 * k4 + 1], a1);
            a2 = fmaf(va.z, wc[4 * k4 + 2], a2);
            a3 = fmaf(va.w, wc[4 * k4 + 3], a3);
            c0 = fmaf(vb.x, wc[4 * k4 + 0], c0);
            c1 = fmaf(vb.y, wc[4 * k4 + 1], c1);
            c2 = fmaf(vb.z, wc[4 * k4 + 2], c2);
            c3 = fmaf(vb.w, wc[4 * k4 + 3], c3);
        }
        float accA = (a0 + a1) + (a2 + a3);
        float accB = (c0 + c1) + (c2 + c3);
        accA += __shfl_xor_sync(0xffffffffu, accA, 16);
        accB += __shfl_xor_sync(0xffffffffu, accB, 16);
        if (kh == 0) {
            out[(size_t)i * OUTD + j] = accA + bj;
            if (two) out[(size_t)(i + 1) * OUTD + j] = accB + bj;
        }
    }
}

// ---------------------------------------------------------------------------
extern "C" void kernel_launch(void* const* d_in, const int* in_sizes, int n_in,
                              void* d_out, int out_size) {
    const float* x   = (const float*)d_in[0];
    const int*   ei  = (const int*)d_in[1];     // int32 edge_index [2, E]
    const float* w1l = (const float*)d_in[2];
    const float* b1  = (const float*)d_in[3];
    const float* w1r = (const float*)d_in[4];
    const float* w2l = (const float*)d_in[5];
    const float* b2  = (const float*)d_in[6];
    const float* w2r = (const float*)d_in[7];
    float* out = (float*)d_out;

    int E = in_sizes[1] / 2;
    const int* src = ei;
    const int* dst = ei + E;

    // Layer-1 projections first (independent of CSR)
    k_gemm1<<<888, 256>>>(x, w1l, w1r, NN);

    // CSR build (int atomics only)
    k_init<<<(NN + 511) / 512, 512>>>();
    k_deg <<<(E + 255) / 256, 256>>>(dst, E);
    k_scan<<<1, 1024>>>();
    k_fill<<<(E + 255) / 256, 256>>>(src, dst, E);

    // Aggregations (gather-side, warp per node)
    k_agg<<<(NN + 7) / 8, 256>>>(b1, 0);
    k_agg<<<(NN + 7) / 8, 256>>>(b1, 1);

    // Output GEMV
    k_out<<<888, 256>>>(w2l, w2r, b2, out, NN);
}

// round 7
// speedup vs baseline: 1.4709x; 1.4709x over previous
#include <cuda_runtime.h>
#include <cstdint>
#include <cstddef>

#define NN    100000
#define IND   128
#define HID   64
#define OUTD  128
#define ECAP  1700000
#define SCAN_B 256
#define NPART ((NN + SCAN_B - 1) / SCAN_B)   // 391

// Scratch (device globals — no allocation allowed)
__device__ __align__(16) float g_y1[(size_t)NN * HID];   // x @ w1_l
__device__ __align__(16) float g_xr[(size_t)NN * HID];   // x @ w1_r
__device__ __align__(16) float g_h [(size_t)NN * HID];   // layer-1 activations
__device__ __align__(16) float g_mh[(size_t)NN * HID];   // mean of h over neighbors
__device__ __align__(16) float g_rinv[NN];               // 1 / max(deg, 1)
__device__ __align__(16) int   g_deg[NN];
__device__ int   g_cur[NN];
__device__ int   g_off[NN + 1];
__device__ int   g_part[NPART];                          // per-block degree sums
__device__ int   g_poff[NPART];                          // exclusive scan of partials
__device__ int   g_eidx[ECAP];                           // src node per CSR slot

// ---------------------------------------------------------------------------
__global__ void k_init() {
    int i = blockIdx.x * blockDim.x + threadIdx.x;
    if (i < NN) { g_deg[i] = 0; g_cur[i] = 0; }
}

__global__ void k_deg(const int* __restrict__ dst, int E) {
    int e = blockIdx.x * blockDim.x + threadIdx.x;
    if (e < E) {
        int d = dst[e];
        if (d >= 0 && d < NN) atomicAdd(&g_deg[d], 1);
    }
}

// ---------------------------------------------------------------------------
// Multi-block scan, phase 1: per-block degree sums (391 blocks x 256).
// ---------------------------------------------------------------------------
__global__ __launch_bounds__(SCAN_B) void k_scan_part() {
    __shared__ int sred[SCAN_B];
    int t = threadIdx.x;
    int i = blockIdx.x * SCAN_B + t;
    int v = (i < NN) ? g_deg[i] : 0;
    sred[t] = v;
    __syncthreads();
#pragma unroll
    for (int s = SCAN_B / 2; s > 0; s >>= 1) {
        if (t < s) sred[t] += sred[t + s];
        __syncthreads();
    }
    if (t == 0) g_part[blockIdx.x] = sred[0];
}

// Phase 2: single block scans the 391 partials (exclusive).
__global__ __launch_bounds__(512) void k_scan_top() {
    __shared__ int ss[512];
    int t = threadIdx.x;
    ss[t] = (t < NPART) ? g_part[t] : 0;
    __syncthreads();
#pragma unroll
    for (int d = 1; d < 512; d <<= 1) {
        int v = (t >= d) ? ss[t - d] : 0;
        __syncthreads();
        ss[t] += v;
        __syncthreads();
    }
    if (t < NPART) g_poff[t] = (t == 0) ? 0 : ss[t - 1];
}

// Phase 3: per-block exclusive scan + write g_off / g_rinv.
__global__ __launch_bounds__(SCAN_B) void k_scan_off() {
    __shared__ int ss[SCAN_B];
    int t = threadIdx.x;
    int i = blockIdx.x * SCAN_B + t;
    int d = (i < NN) ? g_deg[i] : 0;
    ss[t] = d;
    __syncthreads();
#pragma unroll
    for (int s = 1; s < SCAN_B; s <<= 1) {
        int v = (t >= s) ? ss[t - s] : 0;
        __syncthreads();
        ss[t] += v;
        __syncthreads();
    }
    if (i < NN) {
        int incl = ss[t];
        int off = g_poff[blockIdx.x] + incl - d;   // exclusive
        g_off[i] = off;
        g_rinv[i] = 1.0f / fmaxf((float)d, 1.0f);
        if (i == NN - 1) g_off[NN] = off + d;
    }
}

__global__ void k_fill(const int* __restrict__ src,
                       const int* __restrict__ dst, int E) {
    int e = blockIdx.x * blockDim.x + threadIdx.x;
    if (e >= E) return;
    int d = dst[e];
    int s = src[e];
    if (d < 0 || d >= NN || s < 0 || s >= NN) return;
    int pos = g_off[d] + atomicAdd(&g_cur[d], 1);
    if (pos >= 0 && pos < ECAP) g_eidx[pos] = s;
}

// ---------------------------------------------------------------------------
// Layer-1 fused GEMM (1 row/iter — R4-proven config):
//   y1 = x @ w1_l, xr = x @ w1_r   (x:[NN,128], w:[128,64])
// ---------------------------------------------------------------------------
__global__ __launch_bounds__(256) void k_gemm1(
    const float* __restrict__ x,
    const float* __restrict__ w1l,
    const float* __restrict__ w1r,
    int n)
{
    int tid  = threadIdx.x;
    int lane = tid & 31;
    int warp = tid >> 5;
    int j    = warp * 16 + (lane & 15);
    int kh   = lane >> 4;

    const float* w = (j < 64) ? w1l : w1r;
    int col = (j < 64) ? j : (j - 64);

    float wc[64];
#pragma unroll
    for (int k = 0; k < 64; k++)
        wc[k] = __ldg(&w[(size_t)(kh * 64 + k) * 64 + col]);

    for (int i = blockIdx.x; i < n; i += gridDim.x) {
        const float4* x4 = (const float4*)(x + (size_t)i * IND + kh * 64);
        float a0 = 0.f, a1 = 0.f, a2 = 0.f, a3 = 0.f;
#pragma unroll
        for (int k4 = 0; k4 < 16; k4++) {
            float4 v = __ldg(x4 + k4);
            a0 = fmaf(v.x, wc[4 * k4 + 0], a0);
            a1 = fmaf(v.y, wc[4 * k4 + 1], a1);
            a2 = fmaf(v.z, wc[4 * k4 + 2], a2);
            a3 = fmaf(v.w, wc[4 * k4 + 3], a3);
        }
        float acc = (a0 + a1) + (a2 + a3);
        acc += __shfl_xor_sync(0xffffffffu, acc, 16);
        if (kh == 0) {
            if (j < 64) g_y1[(size_t)i * HID + j]        = acc;
            else        g_xr[(size_t)i * HID + (j - 64)] = acc;
        }
    }
}

// ---------------------------------------------------------------------------
// Gather-side aggregation, one warp per node, float4 gathers (R6 form).
// ---------------------------------------------------------------------------
__global__ __launch_bounds__(256) void k_agg(const float* __restrict__ b1,
                                             int layer)
{
    int node = blockIdx.x * 8 + (threadIdx.x >> 5);
    if (node >= NN) return;
    int lane = threadIdx.x & 31;
    int q    = lane & 15;     // float4 slot within row
    int half = lane >> 4;     // even/odd edge stream

    const float* val = (layer == 0) ? g_y1 : g_h;
    int beg = g_off[node];
    int end = g_off[node + 1];

    float4 A = {0.f, 0.f, 0.f, 0.f};
    float4 B = {0.f, 0.f, 0.f, 0.f};
    int e = beg + half;
    for (; e + 2 < end; e += 4) {
        int s0 = __ldg(&g_eidx[e]);
        int s1 = __ldg(&g_eidx[e + 2]);
        float4 v0 = __ldg((const float4*)(val + (size_t)s0 * HID) + q);
        float4 v1 = __ldg((const float4*)(val + (size_t)s1 * HID) + q);
        A.x += v0.x; A.y += v0.y; A.z += v0.z; A.w += v0.w;
        B.x += v1.x; B.y += v1.y; B.z += v1.z; B.w += v1.w;
    }
    if (e < end) {
        int s = __ldg(&g_eidx[e]);
        float4 v = __ldg((const float4*)(val + (size_t)s * HID) + q);
        A.x += v.x; A.y += v.y; A.z += v.z; A.w += v.w;
    }
    float4 acc;
    acc.x = A.x + B.x; acc.y = A.y + B.y; acc.z = A.z + B.z; acc.w = A.w + B.w;
    acc.x += __shfl_xor_sync(0xffffffffu, acc.x, 16);
    acc.y += __shfl_xor_sync(0xffffffffu, acc.y, 16);
    acc.z += __shfl_xor_sync(0xffffffffu, acc.z, 16);
    acc.w += __shfl_xor_sync(0xffffffffu, acc.w, 16);

    if (half == 0) {
        float r = g_rinv[node];
        if (layer == 0) {
            float4 xv = ((const float4*)(g_xr + (size_t)node * HID))[q];
            float4 bb = __ldg((const float4*)b1 + q);
            float4 h;
            h.x = fmaxf(fmaf(acc.x, r, bb.x + xv.x), 0.f);
            h.y = fmaxf(fmaf(acc.y, r, bb.y + xv.y), 0.f);
            h.z = fmaxf(fmaf(acc.z, r, bb.z + xv.z), 0.f);
            h.w = fmaxf(fmaf(acc.w, r, bb.w + xv.w), 0.f);
            ((float4*)(g_h + (size_t)node * HID))[q] = h;
        } else {
            float4 m;
            m.x = acc.x * r; m.y = acc.y * r; m.z = acc.z * r; m.w = acc.w * r;
            ((float4*)(g_mh + (size_t)node * HID))[q] = m;
        }
    }
}

// ---------------------------------------------------------------------------
// Layer-2 fused output (1 row/iter — R4-proven config):
//   out = g_mh @ w2_l + b2 + g_h @ w2_r
// ---------------------------------------------------------------------------
__global__ __launch_bounds__(256) void k_out(
    const float* __restrict__ w2l,
    const float* __restrict__ w2r,
    const float* __restrict__ b2,
    float* __restrict__ out,
    int n)
{
    int tid  = threadIdx.x;
    int lane = tid & 31;
    int warp = tid >> 5;
    int j    = warp * 16 + (lane & 15);
    int kh   = lane >> 4;

    const float* w = (kh == 0) ? w2l : w2r;   // [64,128]
    float wc[64];
#pragma unroll
    for (int k = 0; k < 64; k++)
        wc[k] = __ldg(&w[(size_t)k * 128 + j]);

    float bj = __ldg(b2 + j);
    const float* base = (kh == 0) ? g_mh : g_h;

    for (int i = blockIdx.x; i < n; i += gridDim.x) {
        const float4* s4 = (const float4*)(base + (size_t)i * HID);
        float a0 = 0.f, a1 = 0.f, a2 = 0.f, a3 = 0.f;
#pragma unroll
        for (int k4 = 0; k4 < 16; k4++) {
            float4 v = __ldg(s4 + k4);
            a0 = fmaf(v.x, wc[4 * k4 + 0], a0);
            a1 = fmaf(v.y, wc[4 * k4 + 1], a1);
            a2 = fmaf(v.z, wc[4 * k4 + 2], a2);
            a3 = fmaf(v.w, wc[4 * k4 + 3], a3);
        }
        float acc = (a0 + a1) + (a2 + a3);
        acc += __shfl_xor_sync(0xffffffffu, acc, 16);
        if (kh == 0)
            out[(size_t)i * OUTD + j] = acc + bj;
    }
}

// ---------------------------------------------------------------------------
extern "C" void kernel_launch(void* const* d_in, const int* in_sizes, int n_in,
                              void* d_out, int out_size) {
    const float* x   = (const float*)d_in[0];
    const int*   ei  = (const int*)d_in[1];     // int32 edge_index [2, E]
    const float* w1l = (const float*)d_in[2];
    const float* b1  = (const float*)d_in[3];
    const float* w1r = (const float*)d_in[4];
    const float* w2l = (const float*)d_in[5];
    const float* b2  = (const float*)d_in[6];
    const float* w2r = (const float*)d_in[7];
    float* out = (float*)d_out;

    int E = in_sizes[1] / 2;
    const int* src = ei;
    const int* dst = ei + E;

    // Layer-1 projections first (independent of CSR)
    k_gemm1<<<888, 256>>>(x, w1l, w1r, NN);

    // CSR build (int atomics only), multi-block scan
    k_init<<<(NN + 511) / 512, 512>>>();
    k_deg <<<(E + 255) / 256, 256>>>(dst, E);
    k_scan_part<<<NPART, SCAN_B>>>();
    k_scan_top <<<1, 512>>>();
    k_scan_off <<<NPART, SCAN_B>>>();
    k_fill<<<(E + 255) / 256, 256>>>(src, dst, E);

    // Aggregations (gather-side, warp per node)
    k_agg<<<(NN + 7) / 8, 256>>>(b1, 0);
    k_agg<<<(NN + 7) / 8, 256>>>(b1, 1);

    // Output GEMV
    k_out<<<888, 256>>>(w2l, w2r, b2, out, NN);
}